// round 2
// baseline (speedup 1.0000x reference)
#include <cuda_runtime.h>

#define N_NODES 8192
#define N_EDGES 8192
#define DEG 32
#define NNZ (N_EDGES * DEG)
#define D 32
#define FULL 0xffffffffu

// ---------------- scratch (device globals; no allocation) ----------------
__device__ int   g_dedup[NNZ];          // node index or -1 if duplicate within edge
__device__ float g_x0b[N_NODES * D];    // x_0 after layer 1
__device__ float g_x0c[N_NODES * D];    // x_0 after layer 2
__device__ float g_x1b[N_EDGES * D];    // x_1 after second inc.T
__device__ float g_a[N_NODES];          // per-node scalar
__device__ float g_b[N_EDGES];          // per-edge scalar
__device__ float g_u[2 * D];            // collapsed MLP weights (node half, edge half)
__device__ float g_c;                   // collapsed MLP bias

// ---------------- kernels ----------------

// Zero the 256MB output with vectorized stores.
__global__ void k_zero_out(float4* __restrict__ out, int n4) {
    int i = blockIdx.x * blockDim.x + threadIdx.x;
    int stride = gridDim.x * blockDim.x;
    float4 z = make_float4(0.f, 0.f, 0.f, 0.f);
    for (; i < n4; i += stride) out[i] = z;
}

// Zero the two scatter-target scratch buffers.
__global__ void k_zero_scratch() {
    int i = blockIdx.x * blockDim.x + threadIdx.x;
    if (i < N_NODES * D) { g_x0b[i] = 0.f; g_x0c[i] = 0.f; }
}

// Per-edge dedup: warp = one hyperedge (entries are 32-aligned).
// Keep first occurrence of each node within the edge, else -1.
__global__ void k_dedup(const int* __restrict__ node_idx) {
    int i = blockIdx.x * blockDim.x + threadIdx.x;   // i < NNZ
    int lane = threadIdx.x & 31;
    int v = node_idx[i];
    unsigned m = __match_any_sync(FULL, v);
    bool first = ((m & ((1u << lane) - 1u)) == 0u);
    g_dedup[i] = first ? v : -1;
}

// Collapse the affine MLP:  vals = [x0c[n] ; x1b[e]] . v1 + c
// v3 = Wm3 (32), v2 = Wm2 @ v3 (32), v1 = Wm1 @ v2 (64),
// c  = bm1.v2 + bm2.v3 + bm3
__global__ void k_collapse(const float* __restrict__ Wm1, const float* __restrict__ bm1,
                           const float* __restrict__ Wm2, const float* __restrict__ bm2,
                           const float* __restrict__ Wm3, const float* __restrict__ bm3) {
    __shared__ float v2[D];
    int t = threadIdx.x;                 // 0..63
    if (t < D) {
        float s = 0.f;
        #pragma unroll
        for (int j = 0; j < D; j++) s += Wm2[t * D + j] * Wm3[j];
        v2[t] = s;
    }
    __syncthreads();
    {
        float s = 0.f;
        #pragma unroll
        for (int d = 0; d < D; d++) s += Wm1[t * D + d] * v2[d];
        g_u[t] = s;
    }
    if (t == 0) {
        float c = bm3[0];
        #pragma unroll
        for (int d = 0; d < D; d++) c += bm1[d] * v2[d];
        #pragma unroll
        for (int j = 0; j < D; j++) c += bm2[j] * Wm3[j];
        g_c = c;
    }
}

// One UniGCN level-pair per call. Warp = one hyperedge; lane = feature dim.
//   s[e]  = sum over unique nodes n in e of xin[n]          (inc.T @ xin)
//   t[e]  = s[e] @ W                                         (linear)
//   xout[n] += t[e]  for all unique nodes n in e  (atomics)  (inc @ t)
// pass 0: xin = x0_in,   scatter -> g_x0b
// pass 1: xin = g_x0b,   store s -> g_x1b, scatter -> g_x0c
__global__ void k_edge_pass(const float* __restrict__ x0_in,
                            const float* __restrict__ W, int pass) {
    __shared__ float sW[D * D];
    for (int i = threadIdx.x; i < D * D; i += blockDim.x) sW[i] = W[i];
    __syncthreads();

    int warp = (blockIdx.x * blockDim.x + threadIdx.x) >> 5;   // edge id
    int lane = threadIdx.x & 31;                               // feature dim
    const float* xin = (pass == 0) ? x0_in : g_x0b;
    float* xout = (pass == 0) ? g_x0b : g_x0c;

    int myn = g_dedup[warp * DEG + lane];   // each lane caches one entry's node

    // gather-sum (coalesced 128B rows; tables are L2-resident)
    float s = 0.f;
    #pragma unroll
    for (int k = 0; k < DEG; k++) {
        int n = __shfl_sync(FULL, myn, k);
        if (n >= 0) s += xin[n * D + lane];
    }
    if (pass == 1) g_x1b[warp * D + lane] = s;

    // 32x32 linear via warp shuffles
    float t = 0.f;
    #pragma unroll
    for (int d = 0; d < D; d++) {
        float sd = __shfl_sync(FULL, s, d);
        t += sd * sW[d * D + lane];
    }

    // scatter-add (coalesced 32-float groups)
    #pragma unroll
    for (int k = 0; k < DEG; k++) {
        int n = __shfl_sync(FULL, myn, k);
        if (n >= 0) atomicAdd(&xout[n * D + lane], t);
    }
}

// Per-row dot with the collapsed MLP vector. Warp per row; rows 0..N-1 are
// nodes (x0c . u_node), rows N..N+E-1 are edges (x1b . u_edge).
__global__ void k_rowdot() {
    int warp = (blockIdx.x * blockDim.x + threadIdx.x) >> 5;
    int lane = threadIdx.x & 31;
    const float* row; const float* u; float* outp;
    if (warp < N_NODES) { row = &g_x0c[warp * D]; u = &g_u[0]; outp = &g_a[warp]; }
    else { int e = warp - N_NODES; row = &g_x1b[e * D]; u = &g_u[D]; outp = &g_b[e]; }
    float p = row[lane] * u[lane];
    #pragma unroll
    for (int o = 16; o > 0; o >>= 1) p += __shfl_down_sync(FULL, p, o);
    if (lane == 0) *outp = p;
}

// Final sparse scatter into the dense [N, E] output.
// Duplicates within an edge would write the identical value, so skipping
// them (n < 0) is exact.
__global__ void k_scatter(float* __restrict__ out) {
    int i = blockIdx.x * blockDim.x + threadIdx.x;
    if (i >= NNZ) return;
    int n = g_dedup[i];
    if (n < 0) return;
    int e = i >> 5;
    out[n * N_EDGES + e] = g_a[n] + g_b[e] + g_c;
}

// ---------------- launch ----------------
extern "C" void kernel_launch(void* const* d_in, const int* in_sizes, int n_in,
                              void* d_out, int out_size) {
    const float* x0   = (const float*)d_in[0];
    // d_in[1] = dense incidence (256MB) — intentionally unused
    const float* W_l1 = (const float*)d_in[2];
    const float* W_l2 = (const float*)d_in[3];
    const float* Wm1  = (const float*)d_in[4];
    const float* bm1  = (const float*)d_in[5];
    const float* Wm2  = (const float*)d_in[6];
    const float* bm2  = (const float*)d_in[7];
    const float* Wm3  = (const float*)d_in[8];
    const float* bm3  = (const float*)d_in[9];
    const int* node_idx = (const int*)d_in[10];
    float* out = (float*)d_out;

    // Big zero-fill of the output (dominant cost, ~256MB)
    k_zero_out<<<4096, 256>>>((float4*)out, (N_NODES * N_EDGES) / 4);

    // Small prep
    k_zero_scratch<<<(N_NODES * D + 255) / 256, 256>>>();
    k_dedup<<<NNZ / 256, 256>>>(node_idx);
    k_collapse<<<1, 64>>>(Wm1, bm1, Wm2, bm2, Wm3, bm3);

    // Two UniGCN layers (each: inc.T gather, linear, inc scatter)
    k_edge_pass<<<N_EDGES / 8, 256>>>(x0, W_l1, 0);
    k_edge_pass<<<N_EDGES / 8, 256>>>(x0, W_l2, 1);

    // Collapsed-MLP row scalars for nodes + edges
    k_rowdot<<<(N_NODES + N_EDGES) / 8, 256>>>();

    // Sparse value scatter
    k_scatter<<<NNZ / 256, 256>>>(out);
}

// round 4
// speedup vs baseline: 1.1895x; 1.1895x over previous
#include <cuda_runtime.h>

#define N_NODES 8192
#define N_EDGES 8192
#define DEG 32
#define NNZ (N_EDGES * DEG)
#define D 32
#define FULL 0xffffffffu

// Zero-fill slice split of the 16M-float4 output across the 3 fat kernels.
#define Z1_OFF 0
#define Z1_CNT (4 << 20)
#define Z2_OFF (4 << 20)
#define Z2_CNT (5 << 20)
#define Z3_OFF (9 << 20)
#define Z3_CNT (7 << 20)   // 4M + 5M + 7M = 16M = 8192*8192/4

// ---------------- scratch (device globals; no allocation) ----------------
__device__ __align__(16) int   g_dedup[NNZ];        // node idx or -1 (dup within edge)
__device__ __align__(16) float g_x0b[N_NODES * D];  // x_0 after layer 1 (vector scatter)
__device__ __align__(16) float g_a[N_NODES];        // per-node collapsed-MLP scalar
__device__ __align__(16) float g_b[N_EDGES];        // per-edge collapsed-MLP scalar
__device__ __align__(16) float g_u[2 * D];          // collapsed MLP weights
__device__ float g_c;                               // collapsed MLP bias

// ---------------- k1: prep = zero slice + zero scratch + dedup + collapse ----
__global__ void k_prep(float4* __restrict__ out, const int* __restrict__ node_idx,
                       const float* __restrict__ Wm1, const float* __restrict__ bm1,
                       const float* __restrict__ Wm2, const float* __restrict__ bm2,
                       const float* __restrict__ Wm3, const float* __restrict__ bm3) {
    int tid = blockIdx.x * blockDim.x + threadIdx.x;
    int nth = gridDim.x * blockDim.x;
    float4 z = make_float4(0.f, 0.f, 0.f, 0.f);

    // output zero slice 1
    for (int i = tid; i < Z1_CNT; i += nth) out[Z1_OFF + i] = z;
    // scratch zero: g_x0b (64K float4) + g_a (2K float4)
    float4* sb = (float4*)g_x0b;
    for (int i = tid; i < N_NODES * D / 4; i += nth) sb[i] = z;
    float4* sa = (float4*)g_a;
    for (int i = tid; i < N_NODES / 4; i += nth) sa[i] = z;

    // dedup: warp = one hyperedge (entries 32-aligned); keep first occurrence
    int warp = tid >> 5, lane = tid & 31;
    int nwarp = nth >> 5;
    for (int e = warp; e < N_EDGES; e += nwarp) {
        int v = node_idx[e * DEG + lane];
        unsigned m = __match_any_sync(FULL, v);
        bool first = ((m & ((1u << lane) - 1u)) == 0u);
        g_dedup[e * DEG + lane] = first ? v : -1;
    }

    // collapse affine MLP in ONE warp (shfl-only, no shared memory):
    //   v3 = Wm3;  v2 = Wm2 @ v3;  u = Wm1 @ v2 (64);  c = bm1.v2 + bm2.v3 + bm3
    if (blockIdx.x == gridDim.x - 1 && threadIdx.x < 32) {
        int l = threadIdx.x;
        float w3 = Wm3[l];
        float v2 = 0.f;
        #pragma unroll
        for (int j = 0; j < D; j++) v2 += Wm2[l * D + j] * __shfl_sync(FULL, w3, j);
        float u0 = 0.f, u1 = 0.f;
        #pragma unroll
        for (int d = 0; d < D; d++) {
            float vd = __shfl_sync(FULL, v2, d);
            u0 += Wm1[l * D + d] * vd;          // node half (rows 0..31 of Wm1)
            u1 += Wm1[(l + 32) * D + d] * vd;   // edge half (rows 32..63)
        }
        g_u[l] = u0;
        g_u[l + 32] = u1;
        float p = bm1[l] * v2 + bm2[l] * w3;
        #pragma unroll
        for (int o = 16; o > 0; o >>= 1) p += __shfl_xor_sync(FULL, p, o);
        if (l == 0) g_c = p + bm3[0];
    }
}

// ---------------- k2: UniGCN layer 1 (vector) + zero slice ----------------
// warp = edge:  s = sum_{unique n in e} x0[n]   (inc.T @ x0)
//               t = s @ W_l1
//               g_x0b[n] += t  for unique n     (inc @ .)
__global__ void k_edge1(const float* __restrict__ x0, const float* __restrict__ W,
                        float4* __restrict__ out) {
    __shared__ float sW[D * D];
    for (int i = threadIdx.x; i < D * D; i += blockDim.x) sW[i] = W[i];

    int tid = blockIdx.x * blockDim.x + threadIdx.x;
    int nth = gridDim.x * blockDim.x;
    float4 z = make_float4(0.f, 0.f, 0.f, 0.f);
    for (int i = tid; i < Z2_CNT; i += nth) out[Z2_OFF + i] = z;
    __syncthreads();

    int warp = tid >> 5;   // edge id (grid sized to exactly N_EDGES warps)
    int lane = tid & 31;   // feature dim
    int myn = g_dedup[warp * DEG + lane];

    float s = 0.f;
    #pragma unroll
    for (int k = 0; k < DEG; k++) {
        int n = __shfl_sync(FULL, myn, k);
        if (n >= 0) s += x0[n * D + lane];
    }
    float t = 0.f;
    #pragma unroll
    for (int d = 0; d < D; d++)
        t += __shfl_sync(FULL, s, d) * sW[d * D + lane];
    #pragma unroll
    for (int k = 0; k < DEG; k++) {
        int n = __shfl_sync(FULL, myn, k);
        if (n >= 0) atomicAdd(&g_x0b[n * D + lane], t);
    }
}

// ---------------- k3: UniGCN layer 2, collapsed to scalars + zero slice ----
// s = inc.T gather of g_x0b;  t = s @ W_l2
// b[e] = dot(s, u_edge)                       (x_1 branch of the MLP)
// a[n] += dot(t, u_node) for unique n in e    (x_0 branch, by linearity:
//          dot(sum_e t_e, u) = sum_e dot(t_e, u))
__global__ void k_edge2(const float* __restrict__ W, float4* __restrict__ out) {
    __shared__ float sW[D * D];
    for (int i = threadIdx.x; i < D * D; i += blockDim.x) sW[i] = W[i];

    int tid = blockIdx.x * blockDim.x + threadIdx.x;
    int nth = gridDim.x * blockDim.x;
    float4 z = make_float4(0.f, 0.f, 0.f, 0.f);
    for (int i = tid; i < Z3_CNT; i += nth) out[Z3_OFF + i] = z;
    __syncthreads();

    int warp = tid >> 5;
    int lane = tid & 31;
    int myn = g_dedup[warp * DEG + lane];

    float s = 0.f;
    #pragma unroll
    for (int k = 0; k < DEG; k++) {
        int n = __shfl_sync(FULL, myn, k);
        if (n >= 0) s += g_x0b[n * D + lane];
    }
    float t = 0.f;
    #pragma unroll
    for (int d = 0; d < D; d++)
        t += __shfl_sync(FULL, s, d) * sW[d * D + lane];

    float un = g_u[lane];       // node half
    float ue = g_u[D + lane];   // edge half
    float pb = s * ue;
    float pa = t * un;
    #pragma unroll
    for (int o = 16; o > 0; o >>= 1) {
        pb += __shfl_xor_sync(FULL, pb, o);
        pa += __shfl_xor_sync(FULL, pa, o);
    }
    if (lane == 0) g_b[warp] = pb;
    if (myn >= 0) atomicAdd(&g_a[myn], pa);   // one scalar atomic per unique entry
}

// ---------------- k4: final sparse scatter ----------------
// out[n, e] = a[n] + b[e] + c at incidence nonzeros (dups skipped — identical value)
__global__ void k_final(float* __restrict__ out) {
    int i = blockIdx.x * blockDim.x + threadIdx.x;
    int n = g_dedup[i];
    if (n < 0) return;
    int e = i >> 5;
    out[n * N_EDGES + e] = g_a[n] + g_b[e] + g_c;
}

// ---------------- launch ----------------
extern "C" void kernel_launch(void* const* d_in, const int* in_sizes, int n_in,
                              void* d_out, int out_size) {
    const float* x0   = (const float*)d_in[0];
    // d_in[1] = dense incidence (256MB) — intentionally unused
    const float* W_l1 = (const float*)d_in[2];
    const float* W_l2 = (const float*)d_in[3];
    const float* Wm1  = (const float*)d_in[4];
    const float* bm1  = (const float*)d_in[5];
    const float* Wm2  = (const float*)d_in[6];
    const float* bm2  = (const float*)d_in[7];
    const float* Wm3  = (const float*)d_in[8];
    const float* bm3  = (const float*)d_in[9];
    const int* node_idx = (const int*)d_in[10];
    float* out = (float*)d_out;

    k_prep <<<2048, 256>>>((float4*)out, node_idx, Wm1, bm1, Wm2, bm2, Wm3, bm3);
    k_edge1<<<N_EDGES / 8, 256>>>(x0, W_l1, (float4*)out);
    k_edge2<<<N_EDGES / 8, 256>>>(W_l2, (float4*)out);
    k_final<<<NNZ / 256, 256>>>(out);
}

// round 7
// speedup vs baseline: 1.2862x; 1.0812x over previous
#include <cuda_runtime.h>

#define N_NODES 8192
#define N_EDGES 8192
#define DEG 32
#define NNZ (N_EDGES * DEG)
#define D 32
#define FULL 0xffffffffu

// Zero-fill slice split of the 16M-float4 output across the 3 fat kernels.
#define Z1_OFF 0
#define Z1_CNT (4 << 20)
#define Z2_OFF (4 << 20)
#define Z2_CNT (6 << 20)
#define Z3_OFF (10 << 20)
#define Z3_CNT (6 << 20)   // 4M + 6M + 6M = 16M = 8192*8192/4

// ---------------- scratch (device globals; no allocation) ----------------
__device__ __align__(16) int   g_dedup[NNZ];        // node idx or -1 (dup within edge)
__device__ __align__(16) float g_x0b[N_NODES * D];  // x_0 after layer 1 (vector scatter)
__device__ __align__(16) float g_a[N_NODES];        // per-node collapsed-MLP scalar
__device__ __align__(16) float g_b[N_EDGES];        // per-edge collapsed-MLP scalar
__device__ __align__(16) float g_u[2 * D];          // collapsed MLP weights
__device__ float g_c;                               // collapsed MLP bias

// ---------------- k1: prep = zero slice + zero scratch + dedup + collapse ----
__global__ void k_prep(float4* __restrict__ out, const int* __restrict__ node_idx,
                       const float* __restrict__ Wm1, const float* __restrict__ bm1,
                       const float* __restrict__ Wm2, const float* __restrict__ bm2,
                       const float* __restrict__ Wm3, const float* __restrict__ bm3) {
    int tid = blockIdx.x * blockDim.x + threadIdx.x;
    int nth = gridDim.x * blockDim.x;
    float4 z = make_float4(0.f, 0.f, 0.f, 0.f);

    // output zero slice 1 (streaming — never read again before overwrite)
    for (int i = tid; i < Z1_CNT; i += nth) __stwt(&out[Z1_OFF + i], z);
    // scratch zero: g_x0b (64K float4) + g_a (2K float4) — keep in L2 (hot soon)
    float4* sb = (float4*)g_x0b;
    for (int i = tid; i < N_NODES * D / 4; i += nth) sb[i] = z;
    float4* sa = (float4*)g_a;
    for (int i = tid; i < N_NODES / 4; i += nth) sa[i] = z;

    // dedup: warp = one hyperedge (entries 32-aligned); keep first occurrence
    int warp = tid >> 5, lane = tid & 31;
    int nwarp = nth >> 5;
    for (int e = warp; e < N_EDGES; e += nwarp) {
        int v = node_idx[e * DEG + lane];
        unsigned m = __match_any_sync(FULL, v);
        bool first = ((m & ((1u << lane) - 1u)) == 0u);
        g_dedup[e * DEG + lane] = first ? v : -1;
    }

    // collapse affine MLP in ONE warp (shfl-only):
    //   v3 = Wm3;  v2 = Wm2 @ v3;  u = Wm1 @ v2 (64);  c = bm1.v2 + bm2.v3 + bm3
    if (blockIdx.x == gridDim.x - 1 && threadIdx.x < 32) {
        int l = threadIdx.x;
        float w3 = Wm3[l];
        float v2 = 0.f;
        #pragma unroll
        for (int j = 0; j < D; j++) v2 += Wm2[l * D + j] * __shfl_sync(FULL, w3, j);
        float u0 = 0.f, u1 = 0.f;
        #pragma unroll
        for (int d = 0; d < D; d++) {
            float vd = __shfl_sync(FULL, v2, d);
            u0 += Wm1[l * D + d] * vd;          // node half (rows 0..31 of Wm1)
            u1 += Wm1[(l + 32) * D + d] * vd;   // edge half (rows 32..63)
        }
        g_u[l] = u0;
        g_u[l + 32] = u1;
        float p = bm1[l] * v2 + bm2[l] * w3;
        #pragma unroll
        for (int o = 16; o > 0; o >>= 1) p += __shfl_xor_sync(FULL, p, o);
        if (l == 0) g_c = p + bm3[0];
    }
}

// ---------------- k2: UniGCN layer 1 (vector) + zero slice ----------------
// All warps share the zero slice; warps < N_EDGES also do edge work:
//   s = sum_{unique n in e} x0[n];  t = s @ W_l1;  g_x0b[n] += t
__global__ void k_edge1(const float* __restrict__ x0, const float* __restrict__ W,
                        float4* __restrict__ out) {
    __shared__ float sW[D * D];
    for (int i = threadIdx.x; i < D * D; i += blockDim.x) sW[i] = W[i];

    int tid = blockIdx.x * blockDim.x + threadIdx.x;
    int nth = gridDim.x * blockDim.x;
    float4 z = make_float4(0.f, 0.f, 0.f, 0.f);
    for (int i = tid; i < Z2_CNT; i += nth) __stwt(&out[Z2_OFF + i], z);
    __syncthreads();

    int warp = tid >> 5;
    int lane = tid & 31;
    if (warp >= N_EDGES) return;
    int myn = g_dedup[warp * DEG + lane];

    float s = 0.f;
    #pragma unroll
    for (int k = 0; k < DEG; k++) {
        int n = __shfl_sync(FULL, myn, k);
        if (n >= 0) s += x0[n * D + lane];
    }
    float t = 0.f;
    #pragma unroll
    for (int d = 0; d < D; d++)
        t += __shfl_sync(FULL, s, d) * sW[d * D + lane];
    #pragma unroll
    for (int k = 0; k < DEG; k++) {
        int n = __shfl_sync(FULL, myn, k);
        if (n >= 0) atomicAdd(&g_x0b[n * D + lane], t);
    }
}

// ---------------- k3: UniGCN layer 2, collapsed to scalars + zero slice ----
// s = inc.T gather of g_x0b;  t = s @ W_l2
// b[e] = dot(s, u_edge);  a[n] += dot(t, u_node) (linearity)
__global__ void k_edge2(const float* __restrict__ W, float4* __restrict__ out) {
    __shared__ float sW[D * D];
    for (int i = threadIdx.x; i < D * D; i += blockDim.x) sW[i] = W[i];

    int tid = blockIdx.x * blockDim.x + threadIdx.x;
    int nth = gridDim.x * blockDim.x;
    float4 z = make_float4(0.f, 0.f, 0.f, 0.f);
    for (int i = tid; i < Z3_CNT; i += nth) __stwt(&out[Z3_OFF + i], z);
    __syncthreads();

    int warp = tid >> 5;
    int lane = tid & 31;
    if (warp >= N_EDGES) return;
    int myn = g_dedup[warp * DEG + lane];

    float s = 0.f;
    #pragma unroll
    for (int k = 0; k < DEG; k++) {
        int n = __shfl_sync(FULL, myn, k);
        if (n >= 0) s += g_x0b[n * D + lane];
    }
    float t = 0.f;
    #pragma unroll
    for (int d = 0; d < D; d++)
        t += __shfl_sync(FULL, s, d) * sW[d * D + lane];

    float un = g_u[lane];       // node half
    float ue = g_u[D + lane];   // edge half
    float pb = s * ue;
    float pa = t * un;
    #pragma unroll
    for (int o = 16; o > 0; o >>= 1) {
        pb += __shfl_xor_sync(FULL, pb, o);
        pa += __shfl_xor_sync(FULL, pa, o);
    }
    if (lane == 0) g_b[warp] = pb;
    if (myn >= 0) atomicAdd(&g_a[myn], pa);   // one scalar atomic per unique entry
}

// ---------------- k4: final sparse scatter (4 entries/thread ILP) ----------
// Thread i handles entries 4i..4i+3, which never cross an edge boundary,
// so e = i>>3 is thread-uniform. 4 independent a[n] load chains per thread.
__global__ void k_final(float* __restrict__ out) {
    int i = blockIdx.x * blockDim.x + threadIdx.x;   // i < NNZ/4
    int e = i >> 3;
    int4 n4 = ((const int4*)g_dedup)[i];
    float be = g_b[e] + g_c;
    float* rowbase = out + e;   // out[n * N_EDGES + e]
    if (n4.x >= 0) __stwt(&rowbase[(long)n4.x * N_EDGES], g_a[n4.x] + be);
    if (n4.y >= 0) __stwt(&rowbase[(long)n4.y * N_EDGES], g_a[n4.y] + be);
    if (n4.z >= 0) __stwt(&rowbase[(long)n4.z * N_EDGES], g_a[n4.z] + be);
    if (n4.w >= 0) __stwt(&rowbase[(long)n4.w * N_EDGES], g_a[n4.w] + be);
}

// ---------------- launch ----------------
extern "C" void kernel_launch(void* const* d_in, const int* in_sizes, int n_in,
                              void* d_out, int out_size) {
    const float* x0   = (const float*)d_in[0];
    // d_in[1] = dense incidence (256MB) — intentionally unused
    const float* W_l1 = (const float*)d_in[2];
    const float* W_l2 = (const float*)d_in[3];
    const float* Wm1  = (const float*)d_in[4];
    const float* bm1  = (const float*)d_in[5];
    const float* Wm2  = (const float*)d_in[6];
    const float* bm2  = (const float*)d_in[7];
    const float* Wm3  = (const float*)d_in[8];
    const float* bm3  = (const float*)d_in[9];
    const int* node_idx = (const int*)d_in[10];
    float* out = (float*)d_out;

    k_prep <<<2048, 256>>>((float4*)out, node_idx, Wm1, bm1, Wm2, bm2, Wm3, bm3);
    k_edge1<<<2048, 256>>>(x0, W_l1, (float4*)out);
    k_edge2<<<2048, 256>>>(W_l2, (float4*)out);
    k_final<<<NNZ / 4 / 256, 256>>>(out);
}